// round 12
// baseline (speedup 1.0000x reference)
#include <cuda_runtime.h>
#include <cuda_bf16.h>
#include <cstdint>

#define DIM   192
#define HEADS 6
#define HDIM  32
#define NTOK  64
#define NWIN  4096

// ---------------------------------------------------------------------------
// Scratch (static device globals — no allocation in kernel_launch)
// ---------------------------------------------------------------------------
__device__ float g_qkv[(size_t)NWIN * 3 * HEADS * NTOK * HDIM];   // (b,s,h,n,d)
__device__ float g_att[(size_t)NWIN * NTOK * DIM];
__device__ float g_bias[HEADS * NTOK * NTOK];

// ---------------------------------------------------------------------------
// Helpers
// ---------------------------------------------------------------------------
__device__ __forceinline__ uint32_t smem_to_u32(const void* smem_ptr) {
    uint32_t addr;
    asm("{ .reg .u64 tmp; cvta.to.shared.u64 tmp, %1; cvt.u32.u64 %0, tmp; }"
        : "=r"(addr) : "l"(smem_ptr));
    return addr;
}

// ldmatrix x4 (baseline PTX, sm_75+ — no arch suffix needed)
__device__ __forceinline__ void ldm_x4(uint32_t* r, uint32_t addr) {
    asm volatile("ldmatrix.sync.aligned.m8n8.x4.shared.b16 {%0,%1,%2,%3}, [%4];"
                 : "=r"(r[0]), "=r"(r[1]), "=r"(r[2]), "=r"(r[3]) : "r"(addr));
}

// mma.sync m16n8k16 bf16 -> fp32 (baseline PTX, sm_80+)
__device__ __forceinline__ void mma16816(float* c, const uint32_t* a,
                                         uint32_t b0, uint32_t b1) {
    asm volatile(
        "mma.sync.aligned.m16n8k16.row.col.f32.bf16.bf16.f32 "
        "{%0,%1,%2,%3}, {%4,%5,%6,%7}, {%8,%9}, {%0,%1,%2,%3};"
        : "+f"(c[0]), "+f"(c[1]), "+f"(c[2]), "+f"(c[3])
        : "r"(a[0]), "r"(a[1]), "r"(a[2]), "r"(a[3]), "r"(b0), "r"(b1));
}

// ---------------------------------------------------------------------------
// Packed f32x2 helpers (attention kernel)
// ---------------------------------------------------------------------------
__device__ __forceinline__ unsigned long long pk2(float x) {
    unsigned long long r;
    unsigned int b = __float_as_uint(x);
    asm("mov.b64 %0, {%1, %1};" : "=l"(r) : "r"(b));
    return r;
}
__device__ __forceinline__ unsigned long long pk2f(float lo, float hi) {
    unsigned long long r;
    asm("mov.b64 %0, {%1, %2};" : "=l"(r) : "r"(__float_as_uint(lo)), "r"(__float_as_uint(hi)));
    return r;
}
__device__ __forceinline__ float2 upk2(unsigned long long v) {
    unsigned int lo, hi;
    asm("mov.b64 {%0, %1}, %2;" : "=r"(lo), "=r"(hi) : "l"(v));
    return make_float2(__uint_as_float(lo), __uint_as_float(hi));
}
__device__ __forceinline__ void ffma2(unsigned long long& d,
                                      unsigned long long a,
                                      unsigned long long b) {
    asm("fma.rn.f32x2 %0, %1, %2, %0;" : "+l"(d) : "l"(a), "l"(b));
}

// ---------------------------------------------------------------------------
// bf16 hi/lo split of 4 floats, packed for 8-byte smem stores
// ---------------------------------------------------------------------------
__device__ __forceinline__ void split4(float4 v, uint2& hi, uint2& lo) {
    __nv_bfloat16 hx = __float2bfloat16(v.x), hy = __float2bfloat16(v.y);
    __nv_bfloat16 hz = __float2bfloat16(v.z), hw = __float2bfloat16(v.w);
    float rx = v.x - __bfloat162float(hx), ry = v.y - __bfloat162float(hy);
    float rz = v.z - __bfloat162float(hz), rw = v.w - __bfloat162float(hw);
    __nv_bfloat16 lx = __float2bfloat16(rx), ly = __float2bfloat16(ry);
    __nv_bfloat16 lz = __float2bfloat16(rz), lw = __float2bfloat16(rw);
    hi.x = (uint32_t)__bfloat16_as_ushort(hx) | ((uint32_t)__bfloat16_as_ushort(hy) << 16);
    hi.y = (uint32_t)__bfloat16_as_ushort(hz) | ((uint32_t)__bfloat16_as_ushort(hw) << 16);
    lo.x = (uint32_t)__bfloat16_as_ushort(lx) | ((uint32_t)__bfloat16_as_ushort(ly) << 16);
    lo.y = (uint32_t)__bfloat16_as_ushort(lz) | ((uint32_t)__bfloat16_as_ushort(lw) << 16);
}

// ---------------------------------------------------------------------------
// Shared memory layout (byte offsets). Row pitch = 400B (192 bf16 + 8 pad):
// pitch/16 = 25 chunks -> ldmatrix rows land on distinct 4-bank groups
// (4r mod 32), conflict-free.
// ---------------------------------------------------------------------------
#define PITCH      400u
#define A_LO_OFF   51200u          // A hi: [0,51200), A lo: [51200,102400)
#define B_BASE     102400u         // 2 stages x (hi 25600 + lo 25600)
#define B_LO_OFF   25600u
#define B_STRIDE   51200u
#define SMEM_BYTES 204800u

// ---------------------------------------------------------------------------
// K0: materialize relative position bias
// ---------------------------------------------------------------------------
__global__ void bias_kernel(const float* __restrict__ rpb,
                            const int*   __restrict__ rel_idx) {
    int idx = blockIdx.x * blockDim.x + threadIdx.x;
    if (idx < HEADS * NTOK * NTOK) {
        int h = idx / (NTOK * NTOK);
        int r = idx % (NTOK * NTOK);
        g_bias[idx] = rpb[rel_idx[r] * HEADS + h];
    }
}

// ---------------------------------------------------------------------------
// Tensor-core GEMM via mma.sync:  C[128 rows, CT*64 cols] = A(.,192) @ W^T + b
// bf16 hi/lo 3-pass split accumulated in fp32 registers.
// QKV=true: A=x, scatter epilogue into g_qkv (scale q). QKV=false: A=g_att, C=Out.
// ---------------------------------------------------------------------------
template<int CT, bool QKV>
__global__ void __launch_bounds__(256, 1)
gemm_kernel(const float* __restrict__ Ain, const float* __restrict__ W,
            const float* __restrict__ bvec, float* __restrict__ Out)
{
    extern __shared__ __align__(16) char smem[];
    const uint32_t sb = smem_to_u32(smem);
    const int tid = threadIdx.x;
    const int wid = tid >> 5, lid = tid & 31;
    const int rowBase = blockIdx.x * 128;
    const int warpRow = (wid & 3) * 32;
    const int warpCol = (wid >> 2) * 32;

    const float* Asrc = QKV ? Ain : (const float*)g_att;

    // ---- load + split A tile (128 x 192) into hi/lo bf16 ----
#pragma unroll
    for (int i = 0; i < 24; i++) {
        int idx = tid + i * 256;                 // 6144 float4s
        int r = idx / 48, k4 = (idx % 48) * 4;
        float4 v = *(const float4*)(Asrc + (size_t)(rowBase + r) * DIM + k4);
        uint2 hi, lo; split4(v, hi, lo);
        *(uint2*)(smem + r * PITCH + k4 * 2) = hi;
        *(uint2*)(smem + A_LO_OFF + r * PITCH + k4 * 2) = lo;
    }
    // ---- load + split B tile 0 (64 x 192) into stage 0 ----
#pragma unroll
    for (int i = 0; i < 12; i++) {
        int idx = tid + i * 256;                 // 3072 float4s
        int r = idx / 48, k4 = (idx % 48) * 4;
        float4 v = *(const float4*)(W + (size_t)r * DIM + k4);
        uint2 hi, lo; split4(v, hi, lo);
        *(uint2*)(smem + B_BASE + r * PITCH + k4 * 2) = hi;
        *(uint2*)(smem + B_BASE + B_LO_OFF + r * PITCH + k4 * 2) = lo;
    }
    __syncthreads();

    // per-lane ldmatrix address components
    const int lrow = (lid & 7) + ((lid >> 3) & 1) * 8;
    const int lkb  = (lid >> 4) * 16;            // k-offset in bytes
    const uint32_t aoff0 = (uint32_t)((warpRow + lrow) * PITCH) + lkb;
    const uint32_t aoff1 = aoff0 + 16 * PITCH;
    const uint32_t boff0 = (uint32_t)((warpCol + lrow) * PITCH) + lkb;
    const uint32_t boff1 = boff0 + 16 * PITCH;

    for (int ct = 0; ct < CT; ct++) {
        float acc[2][4][4];
#pragma unroll
        for (int mt = 0; mt < 2; mt++)
#pragma unroll
            for (int nt = 0; nt < 4; nt++)
#pragma unroll
                for (int e = 0; e < 4; e++) acc[mt][nt][e] = 0.0f;

        // register-staged prefetch of next B tile (hidden under MMA loop)
        float4 stage[12];
        const bool have_next = (ct + 1 < CT);
        if (have_next) {
#pragma unroll
            for (int i = 0; i < 12; i++) {
                int idx = tid + i * 256;
                int r = idx / 48, k4 = (idx % 48) * 4;
                stage[i] = *(const float4*)(W + (size_t)((ct + 1) * 64 + r) * DIM + k4);
            }
        }

        const uint32_t bstage = B_BASE + (uint32_t)(ct & 1) * B_STRIDE;
#pragma unroll
        for (int pass = 0; pass < 3; pass++) {
            const uint32_t ab = sb + (pass == 2 ? A_LO_OFF : 0u);
            const uint32_t bb = sb + bstage + (pass == 1 ? B_LO_OFF : 0u);
#pragma unroll
            for (int ks = 0; ks < 12; ks++) {
                uint32_t A0[4], A1[4], B0[4], B1[4];
                ldm_x4(A0, ab + aoff0 + ks * 32);
                ldm_x4(A1, ab + aoff1 + ks * 32);
                ldm_x4(B0, bb + boff0 + ks * 32);
                ldm_x4(B1, bb + boff1 + ks * 32);
                mma16816(acc[0][0], A0, B0[0], B0[2]);
                mma16816(acc[0][1], A0, B0[1], B0[3]);
                mma16816(acc[0][2], A0, B1[0], B1[2]);
                mma16816(acc[0][3], A0, B1[1], B1[3]);
                mma16816(acc[1][0], A1, B0[0], B0[2]);
                mma16816(acc[1][1], A1, B0[1], B0[3]);
                mma16816(acc[1][2], A1, B1[0], B1[2]);
                mma16816(acc[1][3], A1, B1[1], B1[3]);
            }
        }

        // convert staged B into the other buffer (readers of it synced last iter)
        if (have_next) {
            const uint32_t bs2 = B_BASE + (uint32_t)((ct + 1) & 1) * B_STRIDE;
#pragma unroll
            for (int i = 0; i < 12; i++) {
                int idx = tid + i * 256;
                int r = idx / 48, k4 = (idx % 48) * 4;
                uint2 hi, lo; split4(stage[i], hi, lo);
                *(uint2*)(smem + bs2 + r * PITCH + k4 * 2) = hi;
                *(uint2*)(smem + bs2 + B_LO_OFF + r * PITCH + k4 * 2) = lo;
            }
        }

        // ---- epilogue ----
        const int g  = lid >> 2;
        const int c2 = (lid & 3) * 2;
#pragma unroll
        for (int mt = 0; mt < 2; mt++) {
            const int r0 = rowBase + warpRow + mt * 16 + g;
#pragma unroll
            for (int nt = 0; nt < 4; nt++) {
                const int colg = ct * 64 + warpCol + nt * 8 + c2;
                const float bv0 = bvec[colg], bv1 = bvec[colg + 1];
                if (QKV) {
                    const int s = colg / DIM, rem = colg % DIM;
                    const int h = rem >> 5, dd = rem & 31;
                    const float mul = (s == 0) ? 0.17677669529663687f : 1.0f;
#pragma unroll
                    for (int hh = 0; hh < 2; hh++) {
                        const int row = r0 + hh * 8;
                        const int bw = row >> 6, n = row & 63;
                        float2 o = make_float2((acc[mt][nt][hh * 2 + 0] + bv0) * mul,
                                               (acc[mt][nt][hh * 2 + 1] + bv1) * mul);
                        *(float2*)(g_qkv + ((((size_t)bw * 3 + s) * HEADS + h) * NTOK + n) * HDIM + dd) = o;
                    }
                } else {
#pragma unroll
                    for (int hh = 0; hh < 2; hh++) {
                        const int row = r0 + hh * 8;
                        float2 o = make_float2(acc[mt][nt][hh * 2 + 0] + bv0,
                                               acc[mt][nt][hh * 2 + 1] + bv1);
                        *(float2*)(Out + (size_t)row * DIM + colg) = o;
                    }
                }
            }
        }
        __syncthreads();
    }
}

// ---------------------------------------------------------------------------
// K2: attention per (window, head) — FFMA2 version (unchanged, passing)
// ---------------------------------------------------------------------------
__global__ void __launch_bounds__(256) attn_kernel() {
    __shared__ float qs [64][36];
    __shared__ float kts[32][66];
    __shared__ float vs [64][36];
    __shared__ float as_[64][66];

    const int tid = threadIdx.x;
    const int bh  = blockIdx.x;
    const int b   = bh / HEADS, h = bh % HEADS;

    const float* qg = g_qkv + (((size_t)(b * 3 + 0) * HEADS + h) * NTOK) * HDIM;
    const float* kg = g_qkv + (((size_t)(b * 3 + 1) * HEADS + h) * NTOK) * HDIM;
    const float* vg = g_qkv + (((size_t)(b * 3 + 2) * HEADS + h) * NTOK) * HDIM;

#pragma unroll
    for (int it = 0; it < 2; it++) {
        int idx = tid + it * 256;
        int n = idx >> 3, c4 = (idx & 7) * 4;
        float4 q4 = *(const float4*)(qg + n * HDIM + c4);
        *(float4*)(&qs[n][c4]) = q4;
        float4 k4 = *(const float4*)(kg + n * HDIM + c4);
        kts[c4 + 0][n] = k4.x; kts[c4 + 1][n] = k4.y;
        kts[c4 + 2][n] = k4.z; kts[c4 + 3][n] = k4.w;
        float4 v4 = *(const float4*)(vg + n * HDIM + c4);
        *(float4*)(&vs[n][c4]) = v4;
    }
    __syncthreads();

    const int tx = tid & 15, ty = tid >> 4;

    unsigned long long acc[4][2];
#pragma unroll
    for (int i = 0; i < 4; i++) {
        int row = ty * 4 + i;
        float4 bb = *(const float4*)(g_bias + h * (NTOK * NTOK) + row * NTOK + tx * 4);
        acc[i][0] = pk2f(bb.x, bb.y);
        acc[i][1] = pk2f(bb.z, bb.w);
    }
#pragma unroll 8
    for (int k = 0; k < HDIM; k++) {
        unsigned long long b0 = *(const unsigned long long*)(&kts[k][tx * 4]);
        unsigned long long b1 = *(const unsigned long long*)(&kts[k][tx * 4 + 2]);
#pragma unroll
        for (int i = 0; i < 4; i++) {
            unsigned long long a = pk2(qs[ty * 4 + i][k]);
            ffma2(acc[i][0], a, b0);
            ffma2(acc[i][1], a, b1);
        }
    }

#pragma unroll
    for (int i = 0; i < 4; i++) {
        float2 p0 = upk2(acc[i][0]), p1 = upk2(acc[i][1]);
        float m = fmaxf(fmaxf(p0.x, p0.y), fmaxf(p1.x, p1.y));
#pragma unroll
        for (int off = 8; off >= 1; off >>= 1)
            m = fmaxf(m, __shfl_xor_sync(0xffffffffu, m, off));
        float e0 = __expf(p0.x - m), e1 = __expf(p0.y - m);
        float e2 = __expf(p1.x - m), e3 = __expf(p1.y - m);
        float ssum = e0 + e1 + e2 + e3;
#pragma unroll
        for (int off = 8; off >= 1; off >>= 1)
            ssum += __shfl_xor_sync(0xffffffffu, ssum, off);
        float inv = 1.0f / ssum;
        int row = ty * 4 + i;
        as_[row][tx * 4 + 0] = e0 * inv;
        as_[row][tx * 4 + 1] = e1 * inv;
        as_[row][tx * 4 + 2] = e2 * inv;
        as_[row][tx * 4 + 3] = e3 * inv;
    }
    __syncthreads();

    const int i   = tid >> 2;
    const int dd0 = (tid & 3) * 8;
    unsigned long long o[4] = {0ULL, 0ULL, 0ULL, 0ULL};
#pragma unroll 8
    for (int j = 0; j < NTOK; j++) {
        unsigned long long a  = pk2(as_[i][j]);
        unsigned long long v0 = *(const unsigned long long*)(&vs[j][dd0]);
        unsigned long long v1 = *(const unsigned long long*)(&vs[j][dd0 + 2]);
        unsigned long long v2 = *(const unsigned long long*)(&vs[j][dd0 + 4]);
        unsigned long long v3 = *(const unsigned long long*)(&vs[j][dd0 + 6]);
        ffma2(o[0], a, v0); ffma2(o[1], a, v1);
        ffma2(o[2], a, v2); ffma2(o[3], a, v3);
    }
    float* dst = g_att + ((size_t)b * NTOK + i) * DIM + h * HDIM + dd0;
    float2 r0 = upk2(o[0]), r1 = upk2(o[1]), r2 = upk2(o[2]), r3 = upk2(o[3]);
    *(float4*)(dst)     = make_float4(r0.x, r0.y, r1.x, r1.y);
    *(float4*)(dst + 4) = make_float4(r2.x, r2.y, r3.x, r3.y);
}

// ---------------------------------------------------------------------------
// Launch
// ---------------------------------------------------------------------------
extern "C" void kernel_launch(void* const* d_in, const int* in_sizes, int n_in,
                              void* d_out, int out_size) {
    (void)in_sizes; (void)n_in; (void)out_size;
    const float* x      = (const float*)d_in[0];
    const float* qkv_w  = (const float*)d_in[1];
    const float* qkv_b  = (const float*)d_in[2];
    const float* proj_w = (const float*)d_in[3];
    const float* proj_b = (const float*)d_in[4];
    const float* rpb    = (const float*)d_in[5];
    const int*   relid  = (const int*)d_in[6];
    float* out = (float*)d_out;

    cudaFuncSetAttribute(gemm_kernel<9, true>,
                         cudaFuncAttributeMaxDynamicSharedMemorySize, SMEM_BYTES);
    cudaFuncSetAttribute(gemm_kernel<3, false>,
                         cudaFuncAttributeMaxDynamicSharedMemorySize, SMEM_BYTES);

    bias_kernel<<<(HEADS * NTOK * NTOK + 255) / 256, 256>>>(rpb, relid);
    gemm_kernel<9, true><<<NWIN * NTOK / 128, 256, SMEM_BYTES>>>(x, qkv_w, qkv_b, nullptr);
    attn_kernel<<<NWIN * HEADS, 256>>>();
    gemm_kernel<3, false><<<NWIN * NTOK / 128, 256, SMEM_BYTES>>>(nullptr, proj_w, proj_b, out);
}

// round 14
// speedup vs baseline: 1.5789x; 1.5789x over previous
#include <cuda_runtime.h>
#include <cuda_bf16.h>
#include <cstdint>

#define DIM   192
#define HEADS 6
#define HDIM  32
#define NTOK  64
#define NWIN  4096

// ---------------------------------------------------------------------------
// Scratch (static device globals — no allocation in kernel_launch)
// ---------------------------------------------------------------------------
__device__ float g_qkv[(size_t)NWIN * 3 * HEADS * NTOK * HDIM];   // (b,s,h,n,d)
__device__ float g_att[(size_t)NWIN * NTOK * DIM];
__device__ float g_bias[HEADS * NTOK * NTOK];
// pre-split weights: [plane hi/lo][col][k] bf16, k contiguous (384B rows)
__device__ __nv_bfloat16 g_wq[2][576 * 192];
__device__ __nv_bfloat16 g_wp[2][192 * 192];

// ---------------------------------------------------------------------------
// Helpers
// ---------------------------------------------------------------------------
__device__ __forceinline__ uint32_t smem_to_u32(const void* smem_ptr) {
    uint32_t addr;
    asm("{ .reg .u64 tmp; cvta.to.shared.u64 tmp, %1; cvt.u32.u64 %0, tmp; }"
        : "=r"(addr) : "l"(smem_ptr));
    return addr;
}
__device__ __forceinline__ void ldm_x4(uint32_t* r, uint32_t addr) {
    asm volatile("ldmatrix.sync.aligned.m8n8.x4.shared.b16 {%0,%1,%2,%3}, [%4];"
                 : "=r"(r[0]), "=r"(r[1]), "=r"(r[2]), "=r"(r[3]) : "r"(addr));
}
__device__ __forceinline__ void ldm_x4_t(uint32_t* r, uint32_t addr) {
    asm volatile("ldmatrix.sync.aligned.m8n8.x4.trans.shared.b16 {%0,%1,%2,%3}, [%4];"
                 : "=r"(r[0]), "=r"(r[1]), "=r"(r[2]), "=r"(r[3]) : "r"(addr));
}
__device__ __forceinline__ void mma16816(float* c, const uint32_t* a,
                                         uint32_t b0, uint32_t b1) {
    asm volatile(
        "mma.sync.aligned.m16n8k16.row.col.f32.bf16.bf16.f32 "
        "{%0,%1,%2,%3}, {%4,%5,%6,%7}, {%8,%9}, {%0,%1,%2,%3};"
        : "+f"(c[0]), "+f"(c[1]), "+f"(c[2]), "+f"(c[3])
        : "r"(a[0]), "r"(a[1]), "r"(a[2]), "r"(a[3]), "r"(b0), "r"(b1));
}
__device__ __forceinline__ void cp16(uint32_t saddr, const void* gptr) {
    asm volatile("cp.async.cg.shared.global [%0], [%1], 16;"
                 :: "r"(saddr), "l"(gptr));
}
#define CP_COMMIT() asm volatile("cp.async.commit_group;" ::: "memory")
#define CP_WAIT0()  asm volatile("cp.async.wait_group 0;" ::: "memory")

// bf16 hi/lo split of 4 floats, packed for 8-byte smem stores
__device__ __forceinline__ void split4(float4 v, uint2& hi, uint2& lo) {
    __nv_bfloat16 hx = __float2bfloat16(v.x), hy = __float2bfloat16(v.y);
    __nv_bfloat16 hz = __float2bfloat16(v.z), hw = __float2bfloat16(v.w);
    float rx = v.x - __bfloat162float(hx), ry = v.y - __bfloat162float(hy);
    float rz = v.z - __bfloat162float(hz), rw = v.w - __bfloat162float(hw);
    __nv_bfloat16 lx = __float2bfloat16(rx), ly = __float2bfloat16(ry);
    __nv_bfloat16 lz = __float2bfloat16(rz), lw = __float2bfloat16(rw);
    hi.x = (uint32_t)__bfloat16_as_ushort(hx) | ((uint32_t)__bfloat16_as_ushort(hy) << 16);
    hi.y = (uint32_t)__bfloat16_as_ushort(hz) | ((uint32_t)__bfloat16_as_ushort(hw) << 16);
    lo.x = (uint32_t)__bfloat16_as_ushort(lx) | ((uint32_t)__bfloat16_as_ushort(ly) << 16);
    lo.y = (uint32_t)__bfloat16_as_ushort(lz) | ((uint32_t)__bfloat16_as_ushort(lw) << 16);
}
__device__ __forceinline__ uint32_t pack_bf16_pair(float a, float b) {
    __nv_bfloat16 ha = __float2bfloat16(a), hb = __float2bfloat16(b);
    return (uint32_t)__bfloat16_as_ushort(ha) | ((uint32_t)__bfloat16_as_ushort(hb) << 16);
}

// ---------------------------------------------------------------------------
// K0a: bias materialization
// ---------------------------------------------------------------------------
__global__ void bias_kernel(const float* __restrict__ rpb,
                            const int*   __restrict__ rel_idx) {
    int idx = blockIdx.x * blockDim.x + threadIdx.x;
    if (idx < HEADS * NTOK * NTOK) {
        int h = idx / (NTOK * NTOK);
        int r = idx % (NTOK * NTOK);
        g_bias[idx] = rpb[rel_idx[r] * HEADS + h];
    }
}
// K0b: weight hi/lo split
__global__ void wsplit_kernel(const float* __restrict__ qkv_w,
                              const float* __restrict__ proj_w) {
    int idx = blockIdx.x * blockDim.x + threadIdx.x;
    if (idx < 576 * 192) {
        float w = qkv_w[idx];
        __nv_bfloat16 hi = __float2bfloat16(w);
        g_wq[0][idx] = hi;
        g_wq[1][idx] = __float2bfloat16(w - __bfloat162float(hi));
    }
    if (idx < 192 * 192) {
        float w = proj_w[idx];
        __nv_bfloat16 hi = __float2bfloat16(w);
        g_wp[0][idx] = hi;
        g_wp[1][idx] = __float2bfloat16(w - __bfloat162float(hi));
    }
}

// ---------------------------------------------------------------------------
// Shared layout for GEMM: pitch 400B (192 bf16 + 8 pad)
// ---------------------------------------------------------------------------
#define PITCH      400u
#define A_LO_OFF   51200u
#define B_BASE     102400u
#define B_LO_OFF   25600u
#define B_STRIDE   51200u
#define SMEM_BYTES 204800u

// ---------------------------------------------------------------------------
// GEMM: C[128 rows, CT*64 cols] = A(.,192) @ W^T + b  (bf16 hi/lo, 3 products)
// ---------------------------------------------------------------------------
template<int CT, bool QKV>
__global__ void __launch_bounds__(256, 1)
gemm_kernel(const float* __restrict__ Ain,
            const float* __restrict__ bvec, float* __restrict__ Out)
{
    extern __shared__ __align__(16) char smem[];
    const uint32_t sb = smem_to_u32(smem);
    const int tid = threadIdx.x;
    const int wid = tid >> 5, lid = tid & 31;
    const int rowBase = blockIdx.x * 128;
    const int warpRow = (wid & 3) * 32;
    const int warpCol = (wid >> 2) * 32;

    const float* Asrc = QKV ? Ain : (const float*)g_att;
    const __nv_bfloat16* whi = QKV ? g_wq[0] : g_wp[0];
    const __nv_bfloat16* wlo = QKV ? g_wq[1] : g_wp[1];

    // prologue: cp.async B tile 0 into stage 0
#pragma unroll
    for (int i = 0; i < 12; i++) {
        int idx = tid + i * 256;
        int plane = idx / 1536, rem = idx - plane * 1536;
        int r = rem / 24, c = rem % 24;
        const __nv_bfloat16* src = (plane ? wlo : whi) + (size_t)r * 192 + c * 8;
        cp16(sb + B_BASE + plane * B_LO_OFF + r * PITCH + c * 16, src);
    }
    CP_COMMIT();

    // A tile load + split (overlaps the cp.async)
#pragma unroll
    for (int i = 0; i < 24; i++) {
        int idx = tid + i * 256;
        int r = idx / 48, k4 = (idx % 48) * 4;
        float4 v = *(const float4*)(Asrc + (size_t)(rowBase + r) * DIM + k4);
        uint2 hi, lo; split4(v, hi, lo);
        *(uint2*)(smem + r * PITCH + k4 * 2) = hi;
        *(uint2*)(smem + A_LO_OFF + r * PITCH + k4 * 2) = lo;
    }
    CP_WAIT0();
    __syncthreads();

    const int lrow = (lid & 7) + ((lid >> 3) & 1) * 8;
    const int lkb  = (lid >> 4) * 16;
    const uint32_t aoff0 = (uint32_t)((warpRow + lrow) * PITCH) + lkb;
    const uint32_t aoff1 = aoff0 + 16 * PITCH;
    const uint32_t boff0 = (uint32_t)((warpCol + lrow) * PITCH) + lkb;
    const uint32_t boff1 = boff0 + 16 * PITCH;

    for (int ct = 0; ct < CT; ct++) {
        // prefetch next B tile into other stage (prev readers synced)
        if (ct + 1 < CT) {
#pragma unroll
            for (int i = 0; i < 12; i++) {
                int idx = tid + i * 256;
                int plane = idx / 1536, rem = idx - plane * 1536;
                int r = rem / 24, c = rem % 24;
                const __nv_bfloat16* src =
                    (plane ? wlo : whi) + (size_t)((ct + 1) * 64 + r) * 192 + c * 8;
                cp16(sb + B_BASE + (uint32_t)((ct + 1) & 1) * B_STRIDE
                        + plane * B_LO_OFF + r * PITCH + c * 16, src);
            }
            CP_COMMIT();
        }

        float acc[2][4][4];
#pragma unroll
        for (int mt = 0; mt < 2; mt++)
#pragma unroll
            for (int nt = 0; nt < 4; nt++)
#pragma unroll
                for (int e = 0; e < 4; e++) acc[mt][nt][e] = 0.0f;

        const uint32_t bbh = sb + B_BASE + (uint32_t)(ct & 1) * B_STRIDE;
        const uint32_t bbl = bbh + B_LO_OFF;
#pragma unroll
        for (int ks = 0; ks < 12; ks++) {
            uint32_t Ah0[4], Ah1[4], Al0[4], Al1[4];
            uint32_t Bh0[4], Bh1[4], Bl0[4], Bl1[4];
            ldm_x4(Ah0, sb + aoff0 + ks * 32);
            ldm_x4(Ah1, sb + aoff1 + ks * 32);
            ldm_x4(Al0, sb + A_LO_OFF + aoff0 + ks * 32);
            ldm_x4(Al1, sb + A_LO_OFF + aoff1 + ks * 32);
            ldm_x4(Bh0, bbh + boff0 + ks * 32);
            ldm_x4(Bh1, bbh + boff1 + ks * 32);
            ldm_x4(Bl0, bbl + boff0 + ks * 32);
            ldm_x4(Bl1, bbl + boff1 + ks * 32);
            // pass hi*hi
            mma16816(acc[0][0], Ah0, Bh0[0], Bh0[2]);
            mma16816(acc[0][1], Ah0, Bh0[1], Bh0[3]);
            mma16816(acc[0][2], Ah0, Bh1[0], Bh1[2]);
            mma16816(acc[0][3], Ah0, Bh1[1], Bh1[3]);
            mma16816(acc[1][0], Ah1, Bh0[0], Bh0[2]);
            mma16816(acc[1][1], Ah1, Bh0[1], Bh0[3]);
            mma16816(acc[1][2], Ah1, Bh1[0], Bh1[2]);
            mma16816(acc[1][3], Ah1, Bh1[1], Bh1[3]);
            // pass hi*lo
            mma16816(acc[0][0], Ah0, Bl0[0], Bl0[2]);
            mma16816(acc[0][1], Ah0, Bl0[1], Bl0[3]);
            mma16816(acc[0][2], Ah0, Bl1[0], Bl1[2]);
            mma16816(acc[0][3], Ah0, Bl1[1], Bl1[3]);
            mma16816(acc[1][0], Ah1, Bl0[0], Bl0[2]);
            mma16816(acc[1][1], Ah1, Bl0[1], Bl0[3]);
            mma16816(acc[1][2], Ah1, Bl1[0], Bl1[2]);
            mma16816(acc[1][3], Ah1, Bl1[1], Bl1[3]);
            // pass lo*hi
            mma16816(acc[0][0], Al0, Bh0[0], Bh0[2]);
            mma16816(acc[0][1], Al0, Bh0[1], Bh0[3]);
            mma16816(acc[0][2], Al0, Bh1[0], Bh1[2]);
            mma16816(acc[0][3], Al0, Bh1[1], Bh1[3]);
            mma16816(acc[1][0], Al1, Bh0[0], Bh0[2]);
            mma16816(acc[1][1], Al1, Bh0[1], Bh0[3]);
            mma16816(acc[1][2], Al1, Bh1[0], Bh1[2]);
            mma16816(acc[1][3], Al1, Bh1[1], Bh1[3]);
        }

        // epilogue
        const int g  = lid >> 2;
        const int c2 = (lid & 3) * 2;
#pragma unroll
        for (int mt = 0; mt < 2; mt++) {
            const int r0 = rowBase + warpRow + mt * 16 + g;
#pragma unroll
            for (int nt = 0; nt < 4; nt++) {
                const int colg = ct * 64 + warpCol + nt * 8 + c2;
                const float bv0 = bvec[colg], bv1 = bvec[colg + 1];
                if (QKV) {
                    const int s = colg / DIM, rem = colg % DIM;
                    const int h = rem >> 5, dd = rem & 31;
                    const float mul = (s == 0) ? 0.17677669529663687f : 1.0f;
#pragma unroll
                    for (int hh = 0; hh < 2; hh++) {
                        const int row = r0 + hh * 8;
                        const int bw = row >> 6, n = row & 63;
                        float2 o = make_float2((acc[mt][nt][hh * 2 + 0] + bv0) * mul,
                                               (acc[mt][nt][hh * 2 + 1] + bv1) * mul);
                        *(float2*)(g_qkv + ((((size_t)bw * 3 + s) * HEADS + h) * NTOK + n) * HDIM + dd) = o;
                    }
                } else {
#pragma unroll
                    for (int hh = 0; hh < 2; hh++) {
                        const int row = r0 + hh * 8;
                        float2 o = make_float2(acc[mt][nt][hh * 2 + 0] + bv0,
                                               acc[mt][nt][hh * 2 + 1] + bv1);
                        *(float2*)(Out + (size_t)row * DIM + colg) = o;
                    }
                }
            }
        }
        if (ct + 1 < CT) {
            CP_WAIT0();
            __syncthreads();
        }
    }
}

// ---------------------------------------------------------------------------
// Attention via mma.sync: one block (128 thr, 4 warps) per (window, head).
// Shared layout (bytes): q/k/v [n][d] pitch 80, hi+lo planes; P [n][j] pitch 144.
// ---------------------------------------------------------------------------
#define AQ_HI 0u
#define AK_HI 10240u
#define AV_HI 20480u
#define APL_HALF 5120u            // lo plane offset within q/k/v
#define AP_HI 30720u
#define AP_LO 39936u
#define ATT_SMEM 49152u
#define VPITCH 80u
#define PPITCH 144u

__global__ void __launch_bounds__(128) attn_kernel() {
    extern __shared__ __align__(16) char smem[];
    const uint32_t sb = smem_to_u32(smem);
    const int tid = threadIdx.x;
    const int wid = tid >> 5, lid = tid & 31;
    const int bh = blockIdx.x;
    const int b = bh / HEADS, h = bh % HEADS;

    // load q,k,v (64x32 fp32 each) -> hi/lo bf16 planes
#pragma unroll
    for (int i = 0; i < 12; i++) {
        int idx = tid + i * 128;            // 1536 float4s
        int mat = idx >> 9, rem = idx & 511;
        int n = rem >> 3, c4 = (rem & 7) * 4;
        float4 v = *(const float4*)(g_qkv +
            ((((size_t)b * 3 + mat) * HEADS + h) * NTOK + n) * HDIM + c4);
        uint2 hi, lo; split4(v, hi, lo);
        uint32_t base = (uint32_t)mat * 10240u + (uint32_t)n * VPITCH + (uint32_t)c4 * 2u;
        *(uint2*)(smem + base) = hi;
        *(uint2*)(smem + base + APL_HALF) = lo;
    }
    __syncthreads();

    const int warpRow = wid * 16;
    const int lrow = (lid & 7) + ((lid >> 3) & 1) * 8;
    const int lkb  = (lid >> 4) * 16;
    const int g  = lid >> 2;
    const int c2 = (lid & 3) * 2;

    // ---- S = q.k^T + bias ----
    float acc[8][4];
    {
        const float* bias = g_bias + h * (NTOK * NTOK);
        const int r0 = warpRow + g;
#pragma unroll
        for (int nt = 0; nt < 8; nt++) {
            float2 b0 = *(const float2*)(bias + r0 * NTOK + nt * 8 + c2);
            float2 b1 = *(const float2*)(bias + (r0 + 8) * NTOK + nt * 8 + c2);
            acc[nt][0] = b0.x; acc[nt][1] = b0.y;
            acc[nt][2] = b1.x; acc[nt][3] = b1.y;
        }
    }
    const uint32_t qoff = sb + AQ_HI + (uint32_t)((warpRow + lrow) * VPITCH + lkb);
#pragma unroll
    for (int ks = 0; ks < 2; ks++) {
        uint32_t Qh[4], Ql[4];
        ldm_x4(Qh, qoff + ks * 32);
        ldm_x4(Ql, qoff + APL_HALF + ks * 32);
#pragma unroll
        for (int nt2 = 0; nt2 < 4; nt2++) {
            uint32_t koff = sb + AK_HI +
                (uint32_t)((nt2 * 16 + lrow) * VPITCH + lkb) + ks * 32;
            uint32_t Kh[4], Kl[4];
            ldm_x4(Kh, koff);
            ldm_x4(Kl, koff + APL_HALF);
            mma16816(acc[2 * nt2 + 0], Qh, Kh[0], Kh[2]);
            mma16816(acc[2 * nt2 + 1], Qh, Kh[1], Kh[3]);
            mma16816(acc[2 * nt2 + 0], Qh, Kl[0], Kl[2]);
            mma16816(acc[2 * nt2 + 1], Qh, Kl[1], Kl[3]);
            mma16816(acc[2 * nt2 + 0], Ql, Kh[0], Kh[2]);
            mma16816(acc[2 * nt2 + 1], Ql, Kh[1], Kh[3]);
        }
    }

    // ---- softmax (rows owned by 4-lane quads) + split P into smem ----
#pragma unroll
    for (int half = 0; half < 2; half++) {
        float m = -1e30f;
#pragma unroll
        for (int nt = 0; nt < 8; nt++)
            m = fmaxf(m, fmaxf(acc[nt][2 * half], acc[nt][2 * half + 1]));
        m = fmaxf(m, __shfl_xor_sync(0xffffffffu, m, 1));
        m = fmaxf(m, __shfl_xor_sync(0xffffffffu, m, 2));
        float ssum = 0.0f;
#pragma unroll
        for (int nt = 0; nt < 8; nt++) {
            float e0 = __expf(acc[nt][2 * half] - m);
            float e1 = __expf(acc[nt][2 * half + 1] - m);
            acc[nt][2 * half] = e0; acc[nt][2 * half + 1] = e1;
            ssum += e0 + e1;
        }
        ssum += __shfl_xor_sync(0xffffffffu, ssum, 1);
        ssum += __shfl_xor_sync(0xffffffffu, ssum, 2);
        float inv = 1.0f / ssum;
        int row = warpRow + g + half * 8;
#pragma unroll
        for (int nt = 0; nt < 8; nt++) {
            float v0 = acc[nt][2 * half] * inv;
            float v1 = acc[nt][2 * half + 1] * inv;
            __nv_bfloat16 h0 = __float2bfloat16(v0), h1 = __float2bfloat16(v1);
            float l0 = v0 - __bfloat162float(h0), l1 = v1 - __bfloat162float(h1);
            uint32_t phi = (uint32_t)__bfloat16_as_ushort(h0)
                         | ((uint32_t)__bfloat16_as_ushort(h1) << 16);
            uint32_t plo = pack_bf16_pair(l0, l1);
            uint32_t off = (uint32_t)(row * PPITCH + (nt * 8 + c2) * 2);
            *(uint32_t*)(smem + AP_HI + off) = phi;
            *(uint32_t*)(smem + AP_LO + off) = plo;
        }
    }
    __syncwarp();

    // ---- O = P.v  (P hi/lo x V hi/lo, 3 products; V via ldmatrix.trans) ----
    float acc2[4][4];
#pragma unroll
    for (int nt = 0; nt < 4; nt++)
#pragma unroll
        for (int e = 0; e < 4; e++) acc2[nt][e] = 0.0f;

    const uint32_t poff = (uint32_t)((warpRow + lrow) * PPITCH + lkb);
    // trans lane address: row = k0 + (lid&7), col byte = (lid>>3)*16
    const uint32_t voff = (uint32_t)((lid & 7) * VPITCH + (lid >> 3) * 16);
#pragma unroll
    for (int ks = 0; ks < 4; ks++) {
        uint32_t Ph[4], Pl[4];
        ldm_x4(Ph, sb + AP_HI + poff + ks * 32);
        ldm_x4(Pl, sb + AP_LO + poff + ks * 32);
        uint32_t v0 = sb + AV_HI + voff + (uint32_t)(ks * 16) * VPITCH;
        uint32_t Vh0[4], Vh1[4], Vl0[4], Vl1[4];
        ldm_x4_t(Vh0, v0);
        ldm_x4_t(Vh1, v0 + 8 * VPITCH);
        ldm_x4_t(Vl0, v0 + APL_HALF);
        ldm_x4_t(Vl1, v0 + APL_HALF + 8 * VPITCH);
#pragma unroll
        for (int nt = 0; nt < 4; nt++) {
            mma16816(acc2[nt], Ph, Vh0[nt], Vh1[nt]);
            mma16816(acc2[nt], Ph, Vl0[nt], Vl1[nt]);
            mma16816(acc2[nt], Pl, Vh0[nt], Vh1[nt]);
        }
    }

    // ---- store O to g_att ----
    const int r0 = warpRow + g;
#pragma unroll
    for (int nt = 0; nt < 4; nt++) {
        int d = nt * 8 + c2;
        *(float2*)(g_att + ((size_t)b * NTOK + r0) * DIM + h * HDIM + d) =
            make_float2(acc2[nt][0], acc2[nt][1]);
        *(float2*)(g_att + ((size_t)b * NTOK + r0 + 8) * DIM + h * HDIM + d) =
            make_float2(acc2[nt][2], acc2[nt][3]);
    }
}

// ---------------------------------------------------------------------------
// Launch
// ---------------------------------------------------------------------------
extern "C" void kernel_launch(void* const* d_in, const int* in_sizes, int n_in,
                              void* d_out, int out_size) {
    (void)in_sizes; (void)n_in; (void)out_size;
    const float* x      = (const float*)d_in[0];
    const float* qkv_w  = (const float*)d_in[1];
    const float* qkv_b  = (const float*)d_in[2];
    const float* proj_w = (const float*)d_in[3];
    const float* proj_b = (const float*)d_in[4];
    const float* rpb    = (const float*)d_in[5];
    const int*   relid  = (const int*)d_in[6];
    float* out = (float*)d_out;

    cudaFuncSetAttribute(gemm_kernel<9, true>,
                         cudaFuncAttributeMaxDynamicSharedMemorySize, SMEM_BYTES);
    cudaFuncSetAttribute(gemm_kernel<3, false>,
                         cudaFuncAttributeMaxDynamicSharedMemorySize, SMEM_BYTES);
    cudaFuncSetAttribute(attn_kernel,
                         cudaFuncAttributeMaxDynamicSharedMemorySize, ATT_SMEM);

    bias_kernel<<<(HEADS * NTOK * NTOK + 255) / 256, 256>>>(rpb, relid);
    wsplit_kernel<<<(576 * 192 + 255) / 256, 256>>>(qkv_w, proj_w);
    gemm_kernel<9, true><<<NWIN * NTOK / 128, 256, SMEM_BYTES>>>(x, qkv_b, nullptr);
    attn_kernel<<<NWIN * HEADS, 128, ATT_SMEM>>>();
    gemm_kernel<3, false><<<NWIN * NTOK / 128, 256, SMEM_BYTES>>>(nullptr, proj_b, out);
}